// round 4
// baseline (speedup 1.0000x reference)
#include <cuda_runtime.h>
#include <cuda_bf16.h>

// SphericalContraction (MipNeRF-360 eq. 10) + per-point 3x3 Jacobian.
//
//   m = ||p||
//   m <= 1 : out = p            J = I
//   m >  1 : s = 2/m - 1/m^2    out = s*p
//            c = 2(1-m)/m^4     J = s*I + c * p p^T
//
// Output layout (out_size = N*12 floats):
//   [0, 3N)   contracted points [N,3]
//   [3N,12N)  jacobians [N,3,3]
//
// R4: streaming cache hints on all global traffic (__ldcs / __stcs) so the
// 192 MiB write-once output doesn't churn L2. Jacobian (75% of stores) staged
// through smem for fully coalesced float4 stores; contracted points stored
// directly (scalar __stcs) to skip their smem round-trip and a barrier.
// 24 KB smem/block -> 8 blocks/SM -> full occupancy.

#define PTS_PER_BLOCK 512
#define THREADS 256

__device__ __forceinline__ void contract_sc(float x, float y, float z,
                                            float& s, float& c) {
    float m2 = fmaf(x, x, fmaf(y, y, z * z));
    bool inside = (m2 <= 1.0f);          // m <= 1  <=>  m^2 <= 1 (no NaN risk)
    float inv  = rsqrtf(m2);             // 1/m (garbage if m2==0; unused then)
    float m    = m2 * inv;               // m
    s          = inv * (2.0f - inv);     // 2/m - 1/m^2
    float inv2 = inv * inv;
    c          = 2.0f * (1.0f - m) * inv2 * inv2;  // 2(1-m)/m^4
    if (inside) { s = 1.0f; c = 0.0f; }  // out = p, J = I
}

__global__ void __launch_bounds__(THREADS)
contract_jac_smem_kernel(const float4* __restrict__ xin4,
                         float* __restrict__ out_c,    // 3N floats
                         float4* __restrict__ out_j4)  // 9N floats as float4
{
    __shared__ float s_in[3 * PTS_PER_BLOCK];   // 6 KB
    __shared__ float s_j[9 * PTS_PER_BLOCK];    // 18 KB

    const int tid = threadIdx.x;
    const size_t base = (size_t)blockIdx.x * PTS_PER_BLOCK;

    // ---- coalesced streaming input load: 384 float4 ----
    const float4* src = xin4 + base * 3 / 4;
    float4* s_in4 = (float4*)s_in;
    s_in4[tid] = __ldcs(&src[tid]);
    if (tid < 128) s_in4[256 + tid] = __ldcs(&src[256 + tid]);
    __syncthreads();

    // ---- compute 2 points per thread (q = tid, tid+256) ----
#pragma unroll
    for (int j = 0; j < 2; ++j) {
        int q = tid + THREADS * j;
        float x = s_in[3 * q + 0];     // stride 3: conflict-free
        float y = s_in[3 * q + 1];
        float z = s_in[3 * q + 2];

        float s, c;
        contract_sc(x, y, z, s, c);

        // contracted point: direct streaming scalar stores (19% of traffic)
        size_t g = base + (size_t)q;
        __stcs(&out_c[3 * g + 0], s * x);
        __stcs(&out_c[3 * g + 1], s * y);
        __stcs(&out_c[3 * g + 2], s * z);

        // jacobian into smem (stride 9: conflict-free)
        float cx = c * x, cy = c * y, cz = c * z;
        float* jr = &s_j[9 * q];
        jr[0] = fmaf(cx, x, s);  jr[1] = cx * y;          jr[2] = cx * z;
        jr[3] = cy * x;          jr[4] = fmaf(cy, y, s);  jr[5] = cy * z;
        jr[6] = cz * x;          jr[7] = cz * y;          jr[8] = fmaf(cz, z, s);
    }
    __syncthreads();

    // ---- coalesced streaming jacobian store: 1152 float4 ----
    const float4* s_j4 = (const float4*)s_j;
    float4* dstj = out_j4 + base * 9 / 4;
#pragma unroll
    for (int i = 0; i < 4; ++i)
        __stcs(&dstj[tid + THREADS * i], s_j4[tid + THREADS * i]);
    if (tid < 128)
        __stcs(&dstj[tid + THREADS * 4], s_j4[tid + THREADS * 4]);
}

// Scalar tail / contract-only fallback.
__global__ void contract_jac_tail_kernel(const float* __restrict__ xin,
                                         float* __restrict__ out_c,
                                         float* __restrict__ out_j,  // may be null
                                         int start, int n) {
    int i = start + blockIdx.x * blockDim.x + threadIdx.x;
    if (i >= n) return;
    float x = xin[3 * i], y = xin[3 * i + 1], z = xin[3 * i + 2];
    float s, c;
    contract_sc(x, y, z, s, c);
    out_c[3 * i + 0] = s * x;
    out_c[3 * i + 1] = s * y;
    out_c[3 * i + 2] = s * z;
    if (out_j) {
        float cx = c * x, cy = c * y, cz = c * z;
        float* jr = &out_j[9 * (size_t)i];
        jr[0] = fmaf(cx, x, s);  jr[1] = cx * y;          jr[2] = cx * z;
        jr[3] = cy * x;          jr[4] = fmaf(cy, y, s);  jr[5] = cy * z;
        jr[6] = cz * x;          jr[7] = cz * y;          jr[8] = fmaf(cz, z, s);
    }
}

extern "C" void kernel_launch(void* const* d_in, const int* in_sizes, int n_in,
                              void* d_out, int out_size) {
    const float* x = (const float*)d_in[0];
    int n = in_sizes[0] / 3;                 // number of points
    float* out_c = (float*)d_out;
    bool want_jac = (out_size >= 12 * n);
    float* out_j = want_jac ? out_c + 3 * (size_t)n : nullptr;

    if (want_jac) {
        int nfull = n / PTS_PER_BLOCK;
        if (nfull > 0) {
            contract_jac_smem_kernel<<<nfull, THREADS>>>(
                (const float4*)x, out_c, (float4*)out_j);
        }
        int done = nfull * PTS_PER_BLOCK;
        if (done < n) {
            int rem = n - done;
            contract_jac_tail_kernel<<<(rem + 255) / 256, 256>>>(
                x, out_c, out_j, done, n);
        }
    } else {
        contract_jac_tail_kernel<<<(n + 255) / 256, 256>>>(
            x, out_c, nullptr, 0, n);
    }
}

// round 5
// speedup vs baseline: 1.0156x; 1.0156x over previous
#include <cuda_runtime.h>
#include <cuda_bf16.h>
#include <cstdint>

// SphericalContraction (MipNeRF-360 eq. 10) + per-point 3x3 Jacobian.
//
//   m = ||p||
//   m <= 1 : out = p            J = I
//   m >  1 : s = 2/m - 1/m^2    out = s*p
//            c = 2(1-m)/m^4     J = s*I + c * p p^T
//
// Output layout (out_size = N*12 floats):
//   [0, 3N)   contracted points [N,3]
//   [3N,12N)  jacobians [N,3,3]
//
// R5: all bulk byte movement via TMA 1D cp.async.bulk (no tensormap needed):
//   - input:  one bulk load GMEM->smem per block (mbarrier complete_tx)
//   - output: two bulk stores smem->GMEM (contracted pts + jacobians)
// The register/LSU path only does the compute-phase smem traffic
// (12B LDS + 48B STS per point); the LDG/STG wavefront load that co-limited
// R3 alongside DRAM is gone. Contracted points overwrite the input smem
// slots in place (each thread touches only its own points).

#define PTS_PER_BLOCK 512
#define THREADS 256

#define IN_BYTES  (3 * PTS_PER_BLOCK * 4)   // 6144
#define JAC_BYTES (9 * PTS_PER_BLOCK * 4)   // 18432

__device__ __forceinline__ uint32_t smem_u32(const void* p) {
    return (uint32_t)__cvta_generic_to_shared(p);
}

__device__ __forceinline__ void contract_sc(float x, float y, float z,
                                            float& s, float& c) {
    float m2 = fmaf(x, x, fmaf(y, y, z * z));
    bool inside = (m2 <= 1.0f);          // m <= 1  <=>  m^2 <= 1 (no NaN risk)
    float inv  = rsqrtf(m2);             // 1/m (garbage if m2==0; unused then)
    float m    = m2 * inv;               // m
    s          = inv * (2.0f - inv);     // 2/m - 1/m^2
    float inv2 = inv * inv;
    c          = 2.0f * (1.0f - m) * inv2 * inv2;  // 2(1-m)/m^4
    if (inside) { s = 1.0f; c = 0.0f; }  // out = p, J = I
}

__global__ void __launch_bounds__(THREADS)
contract_jac_tma_kernel(const float* __restrict__ xin,
                        float* __restrict__ out_c,   // 3N floats
                        float* __restrict__ out_j)   // 9N floats
{
    __shared__ alignas(16) float s_in[3 * PTS_PER_BLOCK];  // 6 KB (reused: oc)
    __shared__ alignas(16) float s_j[9 * PTS_PER_BLOCK];   // 18 KB
    __shared__ alignas(8)  unsigned long long mbar;

    const int tid = threadIdx.x;
    const size_t base = (size_t)blockIdx.x * PTS_PER_BLOCK;
    const uint32_t mbar_a = smem_u32(&mbar);
    const uint32_t sin_a  = smem_u32(s_in);
    const uint32_t sj_a   = smem_u32(s_j);

    // ---- mbarrier init (count 1) ----
    if (tid == 0) {
        asm volatile("mbarrier.init.shared.b64 [%0], %1;"
                     :: "r"(mbar_a), "r"(1u) : "memory");
    }
    __syncthreads();

    // ---- TMA bulk load: input chunk (6 KB) ----
    if (tid == 0) {
        asm volatile("mbarrier.arrive.expect_tx.shared.b64 _, [%0], %1;"
                     :: "r"(mbar_a), "r"((uint32_t)IN_BYTES) : "memory");
        asm volatile(
            "cp.async.bulk.shared::cta.global.mbarrier::complete_tx::bytes "
            "[%0], [%1], %2, [%3];"
            :: "r"(sin_a), "l"(xin + 3 * base), "r"((uint32_t)IN_BYTES),
               "r"(mbar_a) : "memory");
    }

    // ---- wait for load (phase 0) ----
    {
        uint32_t done;
        asm volatile(
            "{\n\t.reg .pred p;\n\t"
            "mbarrier.try_wait.parity.acquire.cta.shared::cta.b64 p, [%1], %2;\n\t"
            "selp.b32 %0, 1, 0, p;\n\t}"
            : "=r"(done) : "r"(mbar_a), "r"(0u) : "memory");
        if (!done) {
            asm volatile(
                "{\n\t.reg .pred P1;\n\t"
                "WL_%=:\n\t"
                "mbarrier.try_wait.parity.acquire.cta.shared::cta.b64 P1, [%0], %1, 0x989680;\n\t"
                "@P1 bra.uni WD_%=;\n\t"
                "bra.uni WL_%=;\n\t"
                "WD_%=:\n\t}"
                :: "r"(mbar_a), "r"(0u) : "memory");
        }
    }

    // ---- compute 2 points per thread (q = tid, tid+256) ----
#pragma unroll
    for (int j = 0; j < 2; ++j) {
        int q = tid + THREADS * j;
        float x = s_in[3 * q + 0];     // stride 3: conflict-free
        float y = s_in[3 * q + 1];
        float z = s_in[3 * q + 2];

        float s, c;
        contract_sc(x, y, z, s, c);

        // contracted point overwrites this thread's own input slots
        s_in[3 * q + 0] = s * x;
        s_in[3 * q + 1] = s * y;
        s_in[3 * q + 2] = s * z;

        // jacobian (stride 9: conflict-free)
        float cx = c * x, cy = c * y, cz = c * z;
        float* jr = &s_j[9 * q];
        jr[0] = fmaf(cx, x, s);  jr[1] = cx * y;          jr[2] = cx * z;
        jr[3] = cy * x;          jr[4] = fmaf(cy, y, s);  jr[5] = cy * z;
        jr[6] = cz * x;          jr[7] = cz * y;          jr[8] = fmaf(cz, z, s);
    }
    __syncthreads();

    // ---- TMA bulk stores: contracted (6 KB) + jacobian (18 KB) ----
    if (tid == 0) {
        asm volatile("fence.proxy.async.shared::cta;" ::: "memory");
        asm volatile(
            "cp.async.bulk.global.shared::cta.bulk_group [%0], [%1], %2;"
            :: "l"(out_c + 3 * base), "r"(sin_a), "r"((uint32_t)IN_BYTES)
            : "memory");
        asm volatile(
            "cp.async.bulk.global.shared::cta.bulk_group [%0], [%1], %2;"
            :: "l"(out_j + 9 * base), "r"(sj_a), "r"((uint32_t)JAC_BYTES)
            : "memory");
        asm volatile("cp.async.bulk.commit_group;" ::: "memory");
        // smem must stay valid until the TMA engine has read it
        asm volatile("cp.async.bulk.wait_group 0;" ::: "memory");
    }
}

// Scalar tail / contract-only fallback.
__global__ void contract_jac_tail_kernel(const float* __restrict__ xin,
                                         float* __restrict__ out_c,
                                         float* __restrict__ out_j,  // may be null
                                         int start, int n) {
    int i = start + blockIdx.x * blockDim.x + threadIdx.x;
    if (i >= n) return;
    float x = xin[3 * i], y = xin[3 * i + 1], z = xin[3 * i + 2];
    float s, c;
    contract_sc(x, y, z, s, c);
    out_c[3 * i + 0] = s * x;
    out_c[3 * i + 1] = s * y;
    out_c[3 * i + 2] = s * z;
    if (out_j) {
        float cx = c * x, cy = c * y, cz = c * z;
        float* jr = &out_j[9 * (size_t)i];
        jr[0] = fmaf(cx, x, s);  jr[1] = cx * y;          jr[2] = cx * z;
        jr[3] = cy * x;          jr[4] = fmaf(cy, y, s);  jr[5] = cy * z;
        jr[6] = cz * x;          jr[7] = cz * y;          jr[8] = fmaf(cz, z, s);
    }
}

extern "C" void kernel_launch(void* const* d_in, const int* in_sizes, int n_in,
                              void* d_out, int out_size) {
    const float* x = (const float*)d_in[0];
    int n = in_sizes[0] / 3;                 // number of points
    float* out_c = (float*)d_out;
    bool want_jac = (out_size >= 12 * n);
    float* out_j = want_jac ? out_c + 3 * (size_t)n : nullptr;

    if (want_jac) {
        int nfull = n / PTS_PER_BLOCK;
        if (nfull > 0) {
            contract_jac_tma_kernel<<<nfull, THREADS>>>(x, out_c, out_j);
        }
        int done = nfull * PTS_PER_BLOCK;
        if (done < n) {
            int rem = n - done;
            contract_jac_tail_kernel<<<(rem + 255) / 256, 256>>>(
                x, out_c, out_j, done, n);
        }
    } else {
        contract_jac_tail_kernel<<<(n + 255) / 256, 256>>>(
            x, out_c, nullptr, 0, n);
    }
}